// round 2
// baseline (speedup 1.0000x reference)
#include <cuda_runtime.h>
#include <mma.h>
#include <cstdint>

using namespace nvcuda;

// ---------------- problem constants ----------------
#define K_DIM   256
#define N_DIM   256
#define M_CTA   128
#define N_CTA   128
#define K_CHUNK 32
#define NUM_CHUNKS 8          // K_DIM / K_CHUNK
#define STAGES  3

#define THREADS 256           // 8 warps: 4 (M) x 2 (N)

// padded smem strides (floats)
#define LDA 40                // 32 data + 8 pad
#define LDB 264               // 256 data + 8 pad
#define LDE 132               // 128 data + 4 pad (epilogue staging)

// smem layout (bytes)
#define OFF_SCALE 0                       // 128 f32
#define OFF_BIAS  512                     // 128 f32
#define OFF_A     1024                    // STAGES * 128 * LDA * 4 = 61440
#define A_STAGE_BYTES (128 * LDA * 4)     // 20480
#define OFF_B     (OFF_A + STAGES * A_STAGE_BYTES)   // 62464
#define B_BYTES   (128 * LDB * 4)         // 135168
#define SMEM_TOTAL (OFF_B + B_BYTES)      // 197632

__device__ __forceinline__ void cp16(void* dst, const void* src) {
    uint32_t d;
    asm("{ .reg .u64 t; cvta.to.shared.u64 t, %1; cvt.u32.u64 %0, t; }"
        : "=r"(d) : "l"(dst));
    asm volatile("cp.async.cg.shared.global [%0], [%1], 16;" :: "r"(d), "l"(src) : "memory");
}
#define CP_COMMIT() asm volatile("cp.async.commit_group;" ::: "memory")
#define CP_WAIT(n)  asm volatile("cp.async.wait_group %0;" :: "n"(n) : "memory")

// Binarized weight (sign(W)) as fp32 (+-1 exact in tf32), prepared per launch.
__device__ __align__(16) float g_bsign[N_DIM * K_DIM];

__global__ void prep_bsign(const float* __restrict__ W) {
    int i = blockIdx.x * blockDim.x + threadIdx.x;
    if (i < N_DIM * K_DIM) {
        float w = W[i];
        g_bsign[i] = (w > 0.f) ? 1.f : ((w < 0.f) ? -1.f : 0.f);
    }
}

__global__ __launch_bounds__(THREADS, 1)
void binlin_gemm(const float* __restrict__ x,
                 const float* __restrict__ scale,
                 const float* __restrict__ bias,
                 float* __restrict__ out) {
    extern __shared__ char smem[];
    float* sScale = (float*)(smem + OFF_SCALE);
    float* sBias  = (float*)(smem + OFF_BIAS);
    float* sB     = (float*)(smem + OFF_B);

    const int tid  = threadIdx.x;
    const int wid  = tid >> 5;
    const int wm   = wid & 3;        // 0..3  (M, 32 rows each)
    const int wn   = wid >> 2;       // 0..1  (N, 64 cols each)

    const int mblk = blockIdx.x >> 1;
    const int nblk = blockIdx.x & 1;
    const int m_base = mblk * M_CTA;
    const int n_base = nblk * N_CTA;

    // ---- scale/bias for this N block into smem ----
    if (tid < 128) {
        sScale[tid] = scale[n_base + tid];
        sBias[tid]  = bias[n_base + tid];
    }

    // ---- prologue: B tile + A chunks 0..2 ----
    // B tile: 128 rows x 256 f32 -> 8192 x 16B chunks, 32 per thread
    {
        const float* bsrc = g_bsign + (size_t)n_base * K_DIM;
        #pragma unroll
        for (int i = 0; i < 32; i++) {
            int c = tid + 256 * i;         // 0..8191
            int row = c >> 6;
            int q   = c & 63;
            cp16((char*)sB + row * (LDB * 4) + q * 16,
                 bsrc + (size_t)row * K_DIM + q * 4);
        }
    }
    // A chunk issuer: 1024 x 16B per chunk, 4 per thread
    const float* xbase = x + (size_t)m_base * K_DIM;
    {
        int c0 = tid * 4;
        #pragma unroll
        for (int s = 0; s < STAGES; s++) {
            char* stg = smem + OFF_A + s * A_STAGE_BYTES;
            #pragma unroll
            for (int i = 0; i < 4; i++) {
                int c = c0 + i;            // 0..1023
                int row = c >> 3;
                int q   = c & 7;
                cp16(stg + row * (LDA * 4) + q * 16,
                     xbase + (size_t)row * K_DIM + s * K_CHUNK + q * 4);
            }
            CP_COMMIT();                   // groups: 0 = B+chunk0, 1, 2
        }
    }

    // ---- accumulators ----
    wmma::fragment<wmma::accumulator, 16, 16, 8, float> c[2][4];
    #pragma unroll
    for (int i = 0; i < 2; i++)
        #pragma unroll
        for (int j = 0; j < 4; j++)
            wmma::fill_fragment(c[i][j], 0.0f);

    // ---- mainloop ----
    #pragma unroll
    for (int s = 0; s < NUM_CHUNKS; s++) {
        if (s <= 5)      CP_WAIT(2);
        else if (s == 6) CP_WAIT(1);
        else             CP_WAIT(0);
        __syncthreads();

        const float* sA = (const float*)(smem + OFF_A + (s % STAGES) * A_STAGE_BYTES);

        #pragma unroll
        for (int kk = 0; kk < 4; kk++) {
            wmma::fragment<wmma::matrix_a, 16, 16, 8, wmma::precision::tf32, wmma::row_major> a[2];
            wmma::fragment<wmma::matrix_b, 16, 16, 8, wmma::precision::tf32, wmma::col_major> b[4];
            #pragma unroll
            for (int i = 0; i < 2; i++) {
                wmma::load_matrix_sync(a[i], sA + (wm * 32 + i * 16) * LDA + kk * 8, LDA);
                #pragma unroll
                for (int t = 0; t < a[i].num_elements; t++)
                    a[i].x[t] = wmma::__float_to_tf32(a[i].x[t]);
            }
            #pragma unroll
            for (int j = 0; j < 4; j++) {
                // B stored [n][k]: col_major view gives 8(k) x 16(n) fragment
                wmma::load_matrix_sync(b[j], sB + (wn * 64 + j * 16) * LDB + s * K_CHUNK + kk * 8, LDB);
                // +-1.0f is exact in tf32: no conversion needed
            }
            #pragma unroll
            for (int i = 0; i < 2; i++)
                #pragma unroll
                for (int j = 0; j < 4; j++)
                    wmma::mma_sync(c[i][j], a[i], b[j], c[i][j]);
        }

        __syncthreads();
        if (s + STAGES < NUM_CHUNKS) {
            char* stg = smem + OFF_A + (s % STAGES) * A_STAGE_BYTES;
            int c0 = tid * 4;
            #pragma unroll
            for (int i = 0; i < 4; i++) {
                int cc = c0 + i;
                int row = cc >> 3;
                int q   = cc & 7;
                cp16(stg + row * (LDA * 4) + q * 16,
                     xbase + (size_t)row * K_DIM + (s + STAGES) * K_CHUNK + q * 4);
            }
            CP_COMMIT();
        }
    }

    // ---- epilogue: stage C through (now dead) B region ----
    __syncthreads();
    float* stageC = sB;   // 128 x LDE(132) floats = 67.6 KB, fits in B region
    #pragma unroll
    for (int i = 0; i < 2; i++)
        #pragma unroll
        for (int j = 0; j < 4; j++)
            wmma::store_matrix_sync(stageC + (wm * 32 + i * 16) * LDE + wn * 64 + j * 16,
                                    c[i][j], LDE, wmma::mem_row_major);
    __syncthreads();

    // 128x128 outputs, 2 threads per row, 64 cols (16 float4) each
    {
        const int r    = tid >> 1;
        const int half = tid & 1;
        const float* src = stageC + r * LDE + half * 64;
        float* dst = out + (size_t)(m_base + r) * N_DIM + n_base + half * 64;
        const float* sc = sScale + half * 64;
        const float* bi = sBias + half * 64;
        #pragma unroll
        for (int q = 0; q < 16; q++) {
            float4 v;
            v.x = src[q * 4 + 0] * sc[q * 4 + 0] + bi[q * 4 + 0];
            v.y = src[q * 4 + 1] * sc[q * 4 + 1] + bi[q * 4 + 1];
            v.z = src[q * 4 + 2] * sc[q * 4 + 2] + bi[q * 4 + 2];
            v.w = src[q * 4 + 3] * sc[q * 4 + 3] + bi[q * 4 + 3];
            *(float4*)(dst + q * 4) = v;
        }
    }
}

extern "C" void kernel_launch(void* const* d_in, const int* in_sizes, int n_in,
                              void* d_out, int out_size) {
    const float* x     = (const float*)d_in[0];
    const float* W     = (const float*)d_in[1];
    const float* scale = (const float*)d_in[2];
    const float* bias  = (const float*)d_in[3];
    float* out = (float*)d_out;

    const int M = in_sizes[0] / K_DIM;             // 131072
    const int grid = (M / M_CTA) * (N_DIM / N_CTA); // 1024 * 2 = 2048

    prep_bsign<<<(N_DIM * K_DIM + 255) / 256, 256>>>(W);

    cudaFuncSetAttribute(binlin_gemm, cudaFuncAttributeMaxDynamicSharedMemorySize, SMEM_TOTAL);
    binlin_gemm<<<grid, THREADS, SMEM_TOTAL>>>(x, scale, bias, out);
}

// round 3
// speedup vs baseline: 1.8872x; 1.8872x over previous
#include <cuda_runtime.h>
#include <cuda_fp16.h>
#include <mma.h>
#include <cstdint>

using namespace nvcuda;

// ---------------- problem constants ----------------
#define K_DIM   256
#define N_DIM   256
#define M_CTA   128
#define THREADS 512           // 16 warps: 4 (M) x 4 (N)

// smem strides (halves / floats)
#define LDA 264               // halves: 256 + 8 pad  (row = 528 B)
#define LDB 264               // halves: 256 + 8 pad
#define LDE 260               // floats: 256 + 4 pad (epilogue staging)

// smem layout (bytes)
#define OFF_SCALE 0
#define OFF_BIAS  1024
#define OFF_A     2048
#define A_BYTES   (128 * LDA * 2)            // 67584
#define OFF_B     (OFF_A + A_BYTES)          // 69632
#define B_BYTES   (256 * LDB * 2)            // 135168
#define SMEM_TOTAL (OFF_B + B_BYTES)         // 204800

__device__ __forceinline__ void cp16(void* dst, const void* src) {
    uint32_t d;
    asm("{ .reg .u64 t; cvta.to.shared.u64 t, %1; cvt.u32.u64 %0, t; }"
        : "=r"(d) : "l"(dst));
    asm volatile("cp.async.cg.shared.global [%0], [%1], 16;" :: "r"(d), "l"(src) : "memory");
}
#define CP_COMMIT() asm volatile("cp.async.commit_group;" ::: "memory")
#define CP_WAIT0()  asm volatile("cp.async.wait_group 0;" ::: "memory")

// Binarized weight sign(W) as fp16 (+-1 exact), prepared per launch.
__device__ __align__(16) __half g_bsign[N_DIM * K_DIM];

__global__ void prep_bsign(const float* __restrict__ W) {
    int i = blockIdx.x * blockDim.x + threadIdx.x;
    if (i < N_DIM * K_DIM) {
        float w = W[i];
        g_bsign[i] = __float2half((w > 0.f) ? 1.f : ((w < 0.f) ? -1.f : 0.f));
    }
}

__global__ __launch_bounds__(THREADS, 1)
void binlin_gemm(const float* __restrict__ x,
                 const float* __restrict__ scale,
                 const float* __restrict__ bias,
                 float* __restrict__ out) {
    extern __shared__ char smem[];
    float*  sScale = (float*)(smem + OFF_SCALE);
    float*  sBias  = (float*)(smem + OFF_BIAS);
    __half* sA     = (__half*)(smem + OFF_A);
    __half* sB     = (__half*)(smem + OFF_B);

    const int tid = threadIdx.x;
    const int wid = tid >> 5;
    const int wm  = wid & 3;        // 0..3  (M, 32 rows each)
    const int wn  = wid >> 2;       // 0..3  (N, 64 cols each)

    const int m_base = blockIdx.x * M_CTA;

    // ---- scale/bias into smem ----
    if (tid < 256) {
        sScale[tid] = scale[tid];
        sBias[tid]  = bias[tid];
    }

    // ---- B tile via cp.async: 256 rows x 512B = 8192 x 16B chunks ----
    #pragma unroll
    for (int i = 0; i < 16; i++) {
        int c   = tid + THREADS * i;        // 0..8191
        int row = c >> 5;
        int q   = c & 31;
        cp16((char*)sB + row * (LDB * 2) + q * 16,
             g_bsign + row * K_DIM + q * 8);
    }
    CP_COMMIT();

    // ---- A tile: LDG fp32 -> cvt -> STS fp16. 8192 float4s, 16/thread ----
    const float* xbase = x + (size_t)m_base * K_DIM;
    #pragma unroll
    for (int i = 0; i < 16; i++) {
        int c   = tid + THREADS * i;        // 0..8191
        int row = c >> 6;                   // 64 float4 per row
        int q   = c & 63;
        float4 v = *(const float4*)(xbase + (size_t)row * K_DIM + q * 4);
        __half2 h0 = __floats2half2_rn(v.x, v.y);
        __half2 h1 = __floats2half2_rn(v.z, v.w);
        *(__half2*)(sA + row * LDA + q * 4)     = h0;
        *(__half2*)(sA + row * LDA + q * 4 + 2) = h1;
    }

    CP_WAIT0();
    __syncthreads();

    // ---- accumulators: warp tile 32(M) x 64(N) ----
    wmma::fragment<wmma::accumulator, 16, 16, 16, float> c[2][4];
    #pragma unroll
    for (int i = 0; i < 2; i++)
        #pragma unroll
        for (int j = 0; j < 4; j++)
            wmma::fill_fragment(c[i][j], 0.0f);

    const __half* aBase = sA + (wm * 32) * LDA;
    const __half* bBase = sB + (wn * 64) * LDB;

    // ---- mainloop: 16 k-steps of 16 ----
    #pragma unroll
    for (int ks = 0; ks < 16; ks++) {
        wmma::fragment<wmma::matrix_a, 16, 16, 16, __half, wmma::row_major> a[2];
        wmma::load_matrix_sync(a[0], aBase + ks * 16, LDA);
        wmma::load_matrix_sync(a[1], aBase + 16 * LDA + ks * 16, LDA);
        #pragma unroll
        for (int j = 0; j < 4; j++) {
            // B stored [n][k]: col_major view gives k x n fragment
            wmma::fragment<wmma::matrix_b, 16, 16, 16, __half, wmma::col_major> b;
            wmma::load_matrix_sync(b, bBase + j * 16 * LDB + ks * 16, LDB);
            wmma::mma_sync(c[0][j], a[0], b, c[0][j]);
            wmma::mma_sync(c[1][j], a[1], b, c[1][j]);
        }
    }

    // ---- epilogue: stage fp32 C through (now dead) B region ----
    __syncthreads();
    float* stageC = (float*)(smem + OFF_B);      // 128 x 260 f32 = 133 KB
    #pragma unroll
    for (int i = 0; i < 2; i++)
        #pragma unroll
        for (int j = 0; j < 4; j++)
            wmma::store_matrix_sync(stageC + (wm * 32 + i * 16) * LDE + wn * 64 + j * 16,
                                    c[i][j], LDE, wmma::mem_row_major);
    __syncthreads();

    // 128 rows x 256 cols, 4 threads per row, 64 cols (16 float4) each
    {
        const int r    = tid >> 2;
        const int quad = tid & 3;
        const float* src = stageC + r * LDE + quad * 64;
        float* dst = out + (size_t)(m_base + r) * N_DIM + quad * 64;
        const float* sc = sScale + quad * 64;
        const float* bi = sBias + quad * 64;
        #pragma unroll
        for (int q = 0; q < 16; q++) {
            float4 v;
            v.x = src[q * 4 + 0] * sc[q * 4 + 0] + bi[q * 4 + 0];
            v.y = src[q * 4 + 1] * sc[q * 4 + 1] + bi[q * 4 + 1];
            v.z = src[q * 4 + 2] * sc[q * 4 + 2] + bi[q * 4 + 2];
            v.w = src[q * 4 + 3] * sc[q * 4 + 3] + bi[q * 4 + 3];
            *(float4*)(dst + q * 4) = v;
        }
    }
}

extern "C" void kernel_launch(void* const* d_in, const int* in_sizes, int n_in,
                              void* d_out, int out_size) {
    const float* x     = (const float*)d_in[0];
    const float* W     = (const float*)d_in[1];
    const float* scale = (const float*)d_in[2];
    const float* bias  = (const float*)d_in[3];
    float* out = (float*)d_out;

    const int M = in_sizes[0] / K_DIM;       // 131072
    const int grid = M / M_CTA;              // 1024

    prep_bsign<<<(N_DIM * K_DIM + 255) / 256, 256>>>(W);

    cudaFuncSetAttribute(binlin_gemm, cudaFuncAttributeMaxDynamicSharedMemorySize, SMEM_TOTAL);
    binlin_gemm<<<grid, THREADS, SMEM_TOTAL>>>(x, scale, bias, out);
}

// round 4
// speedup vs baseline: 2.4463x; 1.2963x over previous
#include <cuda_runtime.h>
#include <cuda_fp16.h>
#include <mma.h>
#include <cstdint>

using namespace nvcuda;

// ---------------- problem constants ----------------
#define K_DIM   256
#define N_DIM   256
#define M_CTA   64
#define N_CTA   128
#define THREADS 256           // 8 warps: 2 (M) x 4 (N), warp tile 32x32

// smem strides
#define LDA 264               // halves: 256 + 8 pad  (row = 528 B)
#define LDB 264               // halves: 256 + 8 pad
#define LDE 132               // floats: 128 + 4 pad (epilogue staging)

// smem layout (bytes)
#define OFF_SCALE 0                          // 128 f32
#define OFF_BIAS  512                        // 128 f32
#define OFF_A     1024
#define A_BYTES   (64 * LDA * 2)             // 33792
#define OFF_B     (OFF_A + A_BYTES)          // 34816
#define B_BYTES   (128 * LDB * 2)            // 67584
#define SMEM_TOTAL (OFF_B + B_BYTES)         // 102400 -> 2 CTAs/SM

__device__ __forceinline__ void cp16(void* dst, const void* src) {
    uint32_t d;
    asm("{ .reg .u64 t; cvta.to.shared.u64 t, %1; cvt.u32.u64 %0, t; }"
        : "=r"(d) : "l"(dst));
    asm volatile("cp.async.cg.shared.global [%0], [%1], 16;" :: "r"(d), "l"(src) : "memory");
}
#define CP_COMMIT() asm volatile("cp.async.commit_group;" ::: "memory")
#define CP_WAIT0()  asm volatile("cp.async.wait_group 0;" ::: "memory")

// Binarized weight sign(W) as fp16 (+-1 exact), prepared per launch.
__device__ __align__(16) __half g_bsign[N_DIM * K_DIM];

__global__ void prep_bsign(const float* __restrict__ W) {
    int i = blockIdx.x * blockDim.x + threadIdx.x;
    if (i < N_DIM * K_DIM) {
        float w = W[i];
        g_bsign[i] = __float2half((w > 0.f) ? 1.f : ((w < 0.f) ? -1.f : 0.f));
    }
}

__global__ __launch_bounds__(THREADS, 2)
void binlin_gemm(const float* __restrict__ x,
                 const float* __restrict__ scale,
                 const float* __restrict__ bias,
                 float* __restrict__ out) {
    extern __shared__ char smem[];
    float*  sScale = (float*)(smem + OFF_SCALE);
    float*  sBias  = (float*)(smem + OFF_BIAS);
    __half* sA     = (__half*)(smem + OFF_A);
    __half* sB     = (__half*)(smem + OFF_B);

    const int tid = threadIdx.x;
    const int wid = tid >> 5;
    const int wm  = wid & 1;        // 0..1  (M, 32 rows each)
    const int wn  = wid >> 1;       // 0..3  (N, 32 cols each)

    const int mblk = blockIdx.x >> 1;
    const int nblk = blockIdx.x & 1;
    const int m_base = mblk * M_CTA;
    const int n_base = nblk * N_CTA;

    // ---- scale/bias for this N block ----
    if (tid < 128) {
        sScale[tid] = scale[n_base + tid];
        sBias[tid]  = bias[n_base + tid];
    }

    // ---- B tile via cp.async: 128 rows x 512B = 4096 x 16B chunks ----
    {
        const __half* bsrc = g_bsign + (size_t)n_base * K_DIM;
        #pragma unroll
        for (int i = 0; i < 16; i++) {
            int c   = tid + THREADS * i;        // 0..4095
            int row = c >> 5;
            int q   = c & 31;
            cp16((char*)sB + row * (LDB * 2) + q * 16,
                 bsrc + row * K_DIM + q * 8);
        }
    }
    CP_COMMIT();

    // ---- A tile: LDG fp32 -> cvt -> STS fp16 (8B stores). 4096 float4 ----
    const float* xbase = x + (size_t)m_base * K_DIM;
    #pragma unroll
    for (int i = 0; i < 16; i++) {
        int c   = tid + THREADS * i;            // 0..4095
        int row = c >> 6;                       // 64 float4 per row
        int q   = c & 63;
        float4 v = *(const float4*)(xbase + (size_t)row * K_DIM + q * 4);
        __half2 h0 = __floats2half2_rn(v.x, v.y);
        __half2 h1 = __floats2half2_rn(v.z, v.w);
        uint2 u;
        u.x = *(uint32_t*)&h0;
        u.y = *(uint32_t*)&h1;
        *(uint2*)(sA + row * LDA + q * 4) = u;
    }

    CP_WAIT0();
    __syncthreads();

    // ---- accumulators: warp tile 32(M) x 32(N) ----
    wmma::fragment<wmma::accumulator, 16, 16, 16, float> c[2][2];
    #pragma unroll
    for (int i = 0; i < 2; i++)
        #pragma unroll
        for (int j = 0; j < 2; j++)
            wmma::fill_fragment(c[i][j], 0.0f);

    const __half* aBase = sA + (wm * 32) * LDA;
    const __half* bBase = sB + (wn * 32) * LDB;

    // ---- mainloop: 16 k-steps of 16 ----
    #pragma unroll
    for (int ks = 0; ks < 16; ks++) {
        wmma::fragment<wmma::matrix_a, 16, 16, 16, __half, wmma::row_major> a[2];
        wmma::fragment<wmma::matrix_b, 16, 16, 16, __half, wmma::col_major> b[2];
        wmma::load_matrix_sync(a[0], aBase + ks * 16, LDA);
        wmma::load_matrix_sync(a[1], aBase + 16 * LDA + ks * 16, LDA);
        wmma::load_matrix_sync(b[0], bBase + ks * 16, LDB);
        wmma::load_matrix_sync(b[1], bBase + 16 * LDB + ks * 16, LDB);
        wmma::mma_sync(c[0][0], a[0], b[0], c[0][0]);
        wmma::mma_sync(c[0][1], a[0], b[1], c[0][1]);
        wmma::mma_sync(c[1][0], a[1], b[0], c[1][0]);
        wmma::mma_sync(c[1][1], a[1], b[1], c[1][1]);
    }

    // ---- epilogue: stage fp32 C through (now dead) B region ----
    __syncthreads();
    float* stageC = (float*)(smem + OFF_B);      // 64 x 132 f32 = 33.8 KB
    #pragma unroll
    for (int i = 0; i < 2; i++)
        #pragma unroll
        for (int j = 0; j < 2; j++)
            wmma::store_matrix_sync(stageC + (wm * 32 + i * 16) * LDE + wn * 32 + j * 16,
                                    c[i][j], LDE, wmma::mem_row_major);
    __syncthreads();

    // 64 rows x 128 cols; row = tid & 63 (conflict-free LDS.128),
    // col group = tid >> 6; each thread: 32 cols = 8 float4 = 128B store
    {
        const int r    = tid & 63;
        const int quad = tid >> 6;              // 0..3
        const float* src = stageC + r * LDE + quad * 32;
        float* dst = out + (size_t)(m_base + r) * N_DIM + n_base + quad * 32;
        const float* sc = sScale + quad * 32;
        const float* bi = sBias + quad * 32;
        #pragma unroll
        for (int q = 0; q < 8; q++) {
            float4 v;
            v.x = src[q * 4 + 0] * sc[q * 4 + 0] + bi[q * 4 + 0];
            v.y = src[q * 4 + 1] * sc[q * 4 + 1] + bi[q * 4 + 1];
            v.z = src[q * 4 + 2] * sc[q * 4 + 2] + bi[q * 4 + 2];
            v.w = src[q * 4 + 3] * sc[q * 4 + 3] + bi[q * 4 + 3];
            *(float4*)(dst + q * 4) = v;
        }
    }
}

extern "C" void kernel_launch(void* const* d_in, const int* in_sizes, int n_in,
                              void* d_out, int out_size) {
    const float* x     = (const float*)d_in[0];
    const float* W     = (const float*)d_in[1];
    const float* scale = (const float*)d_in[2];
    const float* bias  = (const float*)d_in[3];
    float* out = (float*)d_out;

    const int M = in_sizes[0] / K_DIM;              // 131072
    const int grid = (M / M_CTA) * (N_DIM / N_CTA); // 2048 * 2 = 4096

    prep_bsign<<<(N_DIM * K_DIM + 255) / 256, 256>>>(W);

    cudaFuncSetAttribute(binlin_gemm, cudaFuncAttributeMaxDynamicSharedMemorySize, SMEM_TOTAL);
    binlin_gemm<<<grid, THREADS, SMEM_TOTAL>>>(x, scale, bias, out);
}

// round 6
// speedup vs baseline: 3.0357x; 1.2409x over previous
#include <cuda_runtime.h>
#include <cuda_fp16.h>
#include <cstdint>

// ---------------- problem constants ----------------
#define K_DIM   256
#define N_DIM   256
#define M_CTA   64
#define N_CTA   128
#define THREADS 256           // 8 warps: 2 (M) x 4 (N), warp tile 32x32

// smem strides (halves)
#define LDA 264               // 256 + 8 pad  (row = 528 B)
#define LDB 264

// smem layout (bytes)
#define OFF_SCALE 0                          // 128 f32
#define OFF_BIAS  512                        // 128 f32
#define OFF_A     1024
#define A_BYTES   (64 * LDA * 2)             // 33792
#define OFF_B     (OFF_A + A_BYTES)          // 34816
#define B_BYTES   (128 * LDB * 2)            // 67584
#define SMEM_TOTAL (OFF_B + B_BYTES)         // 102400 -> 2 CTAs/SM

__device__ __forceinline__ uint32_t smem_u32(const void* p) {
    uint32_t a;
    asm("{ .reg .u64 t; cvta.to.shared.u64 t, %1; cvt.u32.u64 %0, t; }"
        : "=r"(a) : "l"(p));
    return a;
}
__device__ __forceinline__ void cp16(uint32_t dst, const void* src) {
    asm volatile("cp.async.cg.shared.global [%0], [%1], 16;" :: "r"(dst), "l"(src) : "memory");
}
#define CP_COMMIT() asm volatile("cp.async.commit_group;" ::: "memory")
#define CP_WAIT0()  asm volatile("cp.async.wait_group 0;" ::: "memory")

__device__ __forceinline__ void ldsm4(uint32_t& r0, uint32_t& r1, uint32_t& r2, uint32_t& r3,
                                      uint32_t addr) {
    asm volatile("ldmatrix.sync.aligned.m8n8.x4.shared.b16 {%0,%1,%2,%3}, [%4];"
                 : "=r"(r0), "=r"(r1), "=r"(r2), "=r"(r3) : "r"(addr));
}
__device__ __forceinline__ void mma16816(float* c, const uint32_t* a, uint32_t b0, uint32_t b1) {
    asm volatile(
        "mma.sync.aligned.m16n8k16.row.col.f32.f16.f16.f32 "
        "{%0,%1,%2,%3}, {%4,%5,%6,%7}, {%8,%9}, {%0,%1,%2,%3};"
        : "+f"(c[0]), "+f"(c[1]), "+f"(c[2]), "+f"(c[3])
        : "r"(a[0]), "r"(a[1]), "r"(a[2]), "r"(a[3]), "r"(b0), "r"(b1));
}

// Binarized weight sign(W) as fp16 (+-1 exact), prepared per launch.
__device__ __align__(16) __half g_bsign[N_DIM * K_DIM];

__global__ void prep_bsign(const float* __restrict__ W) {
    int i = blockIdx.x * blockDim.x + threadIdx.x;
    if (i < N_DIM * K_DIM) {
        float w = W[i];
        g_bsign[i] = __float2half((w > 0.f) ? 1.f : ((w < 0.f) ? -1.f : 0.f));
    }
}

__global__ __launch_bounds__(THREADS, 2)
void binlin_gemm(const float* __restrict__ x,
                 const float* __restrict__ scale,
                 const float* __restrict__ bias,
                 float* __restrict__ out) {
    extern __shared__ char smem[];
    float*  sScale = (float*)(smem + OFF_SCALE);
    float*  sBias  = (float*)(smem + OFF_BIAS);
    __half* sA     = (__half*)(smem + OFF_A);
    __half* sB     = (__half*)(smem + OFF_B);
    const uint32_t sAu = smem_u32(sA);
    const uint32_t sBu = smem_u32(sB);

    const int tid  = threadIdx.x;
    const int wid  = tid >> 5;
    const int lane = tid & 31;
    const int wm   = wid & 1;        // 0..1 (M, 32 rows)
    const int wn   = wid >> 1;       // 0..3 (N, 32 cols)

    const int mblk = blockIdx.x >> 1;
    const int nblk = blockIdx.x & 1;
    const int m_base = mblk * M_CTA;
    const int n_base = nblk * N_CTA;

    // ---- scale/bias for this N block ----
    if (tid < 128) {
        sScale[tid] = scale[n_base + tid];
        sBias[tid]  = bias[n_base + tid];
    }

    // ---- B tile via cp.async: 128 rows x 512B = 4096 x 16B chunks ----
    {
        const __half* bsrc = g_bsign + (size_t)n_base * K_DIM;
        #pragma unroll
        for (int i = 0; i < 16; i++) {
            int c   = tid + THREADS * i;        // 0..4095
            int row = c >> 5;
            int q   = c & 31;
            cp16(sBu + row * (LDB * 2) + q * 16, bsrc + row * K_DIM + q * 8);
        }
    }
    CP_COMMIT();

    // ---- A tile: LDG fp32 -> cvt -> STS fp16 (8B). 4096 float4 ----
    const float* xbase = x + (size_t)m_base * K_DIM;
    #pragma unroll
    for (int i = 0; i < 16; i++) {
        int c   = tid + THREADS * i;            // 0..4095
        int row = c >> 6;
        int q   = c & 63;
        float4 v = *(const float4*)(xbase + (size_t)row * K_DIM + q * 4);
        __half2 h0 = __floats2half2_rn(v.x, v.y);
        __half2 h1 = __floats2half2_rn(v.z, v.w);
        uint2 u;
        u.x = *(uint32_t*)&h0;
        u.y = *(uint32_t*)&h1;
        *(uint2*)(sA + row * LDA + q * 4) = u;
    }

    CP_WAIT0();
    __syncthreads();

    // ---- per-thread ldmatrix base addresses ----
    // A (row-major 16x16 tiles): lane&15 -> row, lane>>4 -> k-half (16B)
    const uint32_t aAddr = sAu + ((wm * 32 + (lane & 15)) * LDA + (lane >> 4) * 8) * 2;
    // B stored [n][k]: lane&15 -> n-row, lane>>4 -> k-half
    const uint32_t bAddr = sBu + ((wn * 32 + (lane & 15)) * LDB + (lane >> 4) * 8) * 2;

    float acc[2][4][4];
    #pragma unroll
    for (int i = 0; i < 2; i++)
        #pragma unroll
        for (int j = 0; j < 4; j++)
            #pragma unroll
            for (int e = 0; e < 4; e++)
                acc[i][j][e] = 0.f;

    uint32_t afr[2][2][4];    // [buf][mtile][4 regs]
    // bfr regs: [0]=n0-7/k0-7, [1]=n8-15/k0-7, [2]=n0-7/k8-15, [3]=n8-15/k8-15
    uint32_t bfr[2][2][4];    // [buf][npair][4 regs]

    // prologue: fragments for ks=0
    #pragma unroll
    for (int i = 0; i < 2; i++)
        ldsm4(afr[0][i][0], afr[0][i][1], afr[0][i][2], afr[0][i][3],
              aAddr + i * 16 * LDA * 2);
    #pragma unroll
    for (int p = 0; p < 2; p++)
        ldsm4(bfr[0][p][0], bfr[0][p][1], bfr[0][p][2], bfr[0][p][3],
              bAddr + p * 16 * LDB * 2);

    // ---- mainloop: 16 k-steps of 16, double-buffered fragments ----
    #pragma unroll
    for (int ks = 0; ks < 16; ks++) {
        const int cur = ks & 1;
        const int nxt = cur ^ 1;
        if (ks < 15) {
            const uint32_t ko = (ks + 1) * 32;   // 16 halves = 32 bytes
            #pragma unroll
            for (int i = 0; i < 2; i++)
                ldsm4(afr[nxt][i][0], afr[nxt][i][1], afr[nxt][i][2], afr[nxt][i][3],
                      aAddr + i * 16 * LDA * 2 + ko);
            #pragma unroll
            for (int p = 0; p < 2; p++)
                ldsm4(bfr[nxt][p][0], bfr[nxt][p][1], bfr[nxt][p][2], bfr[nxt][p][3],
                      bAddr + p * 16 * LDB * 2 + ko);
        }
        #pragma unroll
        for (int i = 0; i < 2; i++)
            #pragma unroll
            for (int j = 0; j < 4; j++) {
                const int p = j >> 1, h = j & 1;
                // b0 = k0-7 of n-tile h, b1 = k8-15 of SAME n-tile h
                mma16816(acc[i][j], afr[cur][i], bfr[cur][p][h], bfr[cur][p][h + 2]);
            }
    }

    // ---- register epilogue: scale*acc + bias, direct STG (no smem staging) ----
    const int g = lane >> 2;
    const int t = lane & 3;

    float2 sc[4], bi[4];
    #pragma unroll
    for (int j = 0; j < 4; j++) {
        const int col = wn * 32 + j * 8 + 2 * t;
        sc[j] = *(const float2*)(sScale + col);
        bi[j] = *(const float2*)(sBias + col);
    }

    #pragma unroll
    for (int i = 0; i < 2; i++) {
        const int r0 = m_base + wm * 32 + i * 16 + g;
        float* dst0 = out + (size_t)r0 * N_DIM + n_base + wn * 32;
        float* dst1 = dst0 + 8 * N_DIM;
        #pragma unroll
        for (int j = 0; j < 4; j++) {
            const int col = j * 8 + 2 * t;
            float2 v0, v1;
            v0.x = acc[i][j][0] * sc[j].x + bi[j].x;
            v0.y = acc[i][j][1] * sc[j].y + bi[j].y;
            v1.x = acc[i][j][2] * sc[j].x + bi[j].x;
            v1.y = acc[i][j][3] * sc[j].y + bi[j].y;
            *(float2*)(dst0 + col) = v0;
            *(float2*)(dst1 + col) = v1;
        }
    }
}

extern "C" void kernel_launch(void* const* d_in, const int* in_sizes, int n_in,
                              void* d_out, int out_size) {
    const float* x     = (const float*)d_in[0];
    const float* W     = (const float*)d_in[1];
    const float* scale = (const float*)d_in[2];
    const float* bias  = (const float*)d_in[3];
    float* out = (float*)d_out;

    const int M = in_sizes[0] / K_DIM;              // 131072
    const int grid = (M / M_CTA) * (N_DIM / N_CTA); // 4096

    prep_bsign<<<(N_DIM * K_DIM + 255) / 256, 256>>>(W);

    cudaFuncSetAttribute(binlin_gemm, cudaFuncAttributeMaxDynamicSharedMemorySize, SMEM_TOTAL);
    binlin_gemm<<<grid, THREADS, SMEM_TOTAL>>>(x, scale, bias, out);
}

// round 7
// speedup vs baseline: 3.1625x; 1.0418x over previous
#include <cuda_runtime.h>
#include <cuda_fp16.h>
#include <cstdint>

// ---------------- problem constants ----------------
#define K_DIM   256
#define N_DIM   256
#define M_CTA   128
#define THREADS 512           // 16 warps: 4 (M) x 4 (N), warp tile 32x64

// smem strides (halves)
#define LDA 264               // 256 + 8 pad  (row = 528 B)
#define LDB 264

// smem layout (bytes)
#define OFF_SCALE 0                          // 256 f32
#define OFF_BIAS  1024                       // 256 f32
#define OFF_A     2048
#define A_BYTES   (128 * LDA * 2)            // 67584
#define OFF_B     (OFF_A + A_BYTES)          // 69632
#define B_BYTES   (256 * LDB * 2)            // 135168
#define SMEM_TOTAL (OFF_B + B_BYTES)         // 204800 -> 1 CTA/SM

__device__ __forceinline__ uint32_t smem_u32(const void* p) {
    uint32_t a;
    asm("{ .reg .u64 t; cvta.to.shared.u64 t, %1; cvt.u32.u64 %0, t; }"
        : "=r"(a) : "l"(p));
    return a;
}
__device__ __forceinline__ void cp16(uint32_t dst, const void* src) {
    asm volatile("cp.async.cg.shared.global [%0], [%1], 16;" :: "r"(dst), "l"(src) : "memory");
}
#define CP_COMMIT() asm volatile("cp.async.commit_group;" ::: "memory")
#define CP_WAIT0()  asm volatile("cp.async.wait_group 0;" ::: "memory")

__device__ __forceinline__ void ldsm4(uint32_t& r0, uint32_t& r1, uint32_t& r2, uint32_t& r3,
                                      uint32_t addr) {
    asm volatile("ldmatrix.sync.aligned.m8n8.x4.shared.b16 {%0,%1,%2,%3}, [%4];"
                 : "=r"(r0), "=r"(r1), "=r"(r2), "=r"(r3) : "r"(addr));
}
__device__ __forceinline__ void mma16816(float* c, const uint32_t* a, uint32_t b0, uint32_t b1) {
    asm volatile(
        "mma.sync.aligned.m16n8k16.row.col.f32.f16.f16.f32 "
        "{%0,%1,%2,%3}, {%4,%5,%6,%7}, {%8,%9}, {%0,%1,%2,%3};"
        : "+f"(c[0]), "+f"(c[1]), "+f"(c[2]), "+f"(c[3])
        : "r"(a[0]), "r"(a[1]), "r"(a[2]), "r"(a[3]), "r"(b0), "r"(b1));
}

// Binarized weight sign(W) as fp16 (+-1 exact), prepared per launch.
__device__ __align__(16) __half g_bsign[N_DIM * K_DIM];

__global__ void prep_bsign(const float* __restrict__ W) {
    int i = blockIdx.x * blockDim.x + threadIdx.x;
    if (i < N_DIM * K_DIM) {
        float w = W[i];
        g_bsign[i] = __float2half((w > 0.f) ? 1.f : ((w < 0.f) ? -1.f : 0.f));
    }
}

__global__ __launch_bounds__(THREADS, 1)
void binlin_gemm(const float* __restrict__ x,
                 const float* __restrict__ scale,
                 const float* __restrict__ bias,
                 float* __restrict__ out) {
    extern __shared__ char smem[];
    float*  sScale = (float*)(smem + OFF_SCALE);
    float*  sBias  = (float*)(smem + OFF_BIAS);
    __half* sA     = (__half*)(smem + OFF_A);
    __half* sB     = (__half*)(smem + OFF_B);
    const uint32_t sAu = smem_u32(sA);
    const uint32_t sBu = smem_u32(sB);

    const int tid  = threadIdx.x;
    const int wid  = tid >> 5;
    const int lane = tid & 31;
    const int wm   = wid & 3;        // 0..3 (M, 32 rows each)
    const int wn   = wid >> 2;       // 0..3 (N, 64 cols each)

    const int m_base = blockIdx.x * M_CTA;

    // ---- scale/bias (full N) ----
    if (tid < 256) {
        sScale[tid] = scale[tid];
        sBias[tid]  = bias[tid];
    }

    // ---- B tile via cp.async: 256 rows x 512B = 8192 x 16B chunks ----
    #pragma unroll
    for (int i = 0; i < 16; i++) {
        int c   = tid + THREADS * i;        // 0..8191
        int row = c >> 5;
        int q   = c & 31;
        cp16(sBu + row * (LDB * 2) + q * 16, g_bsign + row * K_DIM + q * 8);
    }
    CP_COMMIT();

    // ---- A tile: LDG fp32 -> cvt -> STS fp16 (8B). 8192 float4 ----
    const float* xbase = x + (size_t)m_base * K_DIM;
    #pragma unroll
    for (int i = 0; i < 16; i++) {
        int c   = tid + THREADS * i;        // 0..8191
        int row = c >> 6;                   // 0..127
        int q   = c & 63;
        float4 v = *(const float4*)(xbase + (size_t)row * K_DIM + q * 4);
        __half2 h0 = __floats2half2_rn(v.x, v.y);
        __half2 h1 = __floats2half2_rn(v.z, v.w);
        uint2 u;
        u.x = *(uint32_t*)&h0;
        u.y = *(uint32_t*)&h1;
        *(uint2*)(sA + row * LDA + q * 4) = u;
    }

    CP_WAIT0();
    __syncthreads();

    // ---- per-thread ldmatrix base addresses ----
    const uint32_t aAddr = sAu + ((wm * 32 + (lane & 15)) * LDA + (lane >> 4) * 8) * 2;
    const uint32_t bAddr = sBu + ((wn * 64 + (lane & 15)) * LDB + (lane >> 4) * 8) * 2;

    // acc[mtile][n8tile][4] : warp tile 32 x 64
    float acc[2][8][4];
    #pragma unroll
    for (int i = 0; i < 2; i++)
        #pragma unroll
        for (int j = 0; j < 8; j++)
            #pragma unroll
            for (int e = 0; e < 4; e++)
                acc[i][j][e] = 0.f;

    uint32_t afr[2][2][4];    // [buf][mtile][4]
    uint32_t bfr[4][4];       // [n16 group][4]  regs: [n0-7/k0-7, n8-15/k0-7, n0-7/k8-15, n8-15/k8-15]

    // prologue: A fragments for ks=0
    #pragma unroll
    for (int i = 0; i < 2; i++)
        ldsm4(afr[0][i][0], afr[0][i][1], afr[0][i][2], afr[0][i][3],
              aAddr + i * 16 * LDA * 2);

    // ---- mainloop: 16 k-steps of 16, A double-buffered ----
    #pragma unroll
    for (int ks = 0; ks < 16; ks++) {
        const int cur = ks & 1;
        const int nxt = cur ^ 1;
        const uint32_t ko = ks * 32;        // 16 halves = 32 bytes

        // B fragments for this k-step (4 n16 groups, issued back-to-back)
        #pragma unroll
        for (int p = 0; p < 4; p++)
            ldsm4(bfr[p][0], bfr[p][1], bfr[p][2], bfr[p][3],
                  bAddr + p * 16 * LDB * 2 + ko);

        if (ks < 15) {
            #pragma unroll
            for (int i = 0; i < 2; i++)
                ldsm4(afr[nxt][i][0], afr[nxt][i][1], afr[nxt][i][2], afr[nxt][i][3],
                      aAddr + i * 16 * LDA * 2 + ko + 32);
        }

        #pragma unroll
        for (int i = 0; i < 2; i++)
            #pragma unroll
            for (int j = 0; j < 8; j++) {
                const int p = j >> 1, h = j & 1;
                mma16816(acc[i][j], afr[cur][i], bfr[p][h], bfr[p][h + 2]);
            }
    }

    // ---- register epilogue: scale*acc + bias, direct STG ----
    const int g = lane >> 2;
    const int t = lane & 3;

    #pragma unroll
    for (int i = 0; i < 2; i++) {
        const int r0 = m_base + wm * 32 + i * 16 + g;
        float* dst0 = out + (size_t)r0 * N_DIM + wn * 64;
        float* dst1 = dst0 + 8 * N_DIM;
        #pragma unroll
        for (int j = 0; j < 8; j++) {
            const int col = j * 8 + 2 * t;
            const float2 sc = *(const float2*)(sScale + wn * 64 + col);
            const float2 bi = *(const float2*)(sBias  + wn * 64 + col);
            float2 v0, v1;
            v0.x = acc[i][j][0] * sc.x + bi.x;
            v0.y = acc[i][j][1] * sc.y + bi.y;
            v1.x = acc[i][j][2] * sc.x + bi.x;
            v1.y = acc[i][j][3] * sc.y + bi.y;
            *(float2*)(dst0 + col) = v0;
            *(float2*)(dst1 + col) = v1;
        }
    }
}

extern "C" void kernel_launch(void* const* d_in, const int* in_sizes, int n_in,
                              void* d_out, int out_size) {
    const float* x     = (const float*)d_in[0];
    const float* W     = (const float*)d_in[1];
    const float* scale = (const float*)d_in[2];
    const float* bias  = (const float*)d_in[3];
    float* out = (float*)d_out;

    const int M = in_sizes[0] / K_DIM;       // 131072
    const int grid = M / M_CTA;              // 1024

    prep_bsign<<<(N_DIM * K_DIM + 255) / 256, 256>>>(W);

    cudaFuncSetAttribute(binlin_gemm, cudaFuncAttributeMaxDynamicSharedMemorySize, SMEM_TOTAL);
    binlin_gemm<<<grid, THREADS, SMEM_TOTAL>>>(x, scale, bias, out);
}

// round 8
// speedup vs baseline: 3.2538x; 1.0289x over previous
#include <cuda_runtime.h>
#include <cuda_fp16.h>
#include <cstdint>

// ---------------- problem constants ----------------
#define K_DIM   256
#define N_DIM   256
#define M_CTA   128
#define THREADS 512           // 16 warps: 4 (M) x 4 (N), warp tile 32x64

#define K_CHUNK 32            // fp32 A chunk (128 B per row)
#define N_CHUNKS 8            // K_DIM / K_CHUNK
#define RING     4            // A chunk ring depth (prefetch 3)

// strides
#define LDB  264              // B: halves, 256 + 8 pad (528 B row)
#define CHF  36               // A chunk: floats per row (144 B)

// smem layout (bytes)
#define OFF_SCALE 0                            // 256 f32
#define OFF_BIAS  1024                         // 256 f32
#define OFF_A     2048
#define CH_BYTES  (128 * CHF * 4)              // 18432
#define OFF_B     (OFF_A + RING * CH_BYTES)    // 75776
#define B_BYTES   (256 * LDB * 2)              // 135168
#define SMEM_TOTAL (OFF_B + B_BYTES)           // 210944 -> 1 CTA/SM

__device__ __forceinline__ uint32_t smem_u32(const void* p) {
    uint32_t a;
    asm("{ .reg .u64 t; cvta.to.shared.u64 t, %1; cvt.u32.u64 %0, t; }"
        : "=r"(a) : "l"(p));
    return a;
}
__device__ __forceinline__ void cp16(uint32_t dst, const void* src) {
    asm volatile("cp.async.cg.shared.global [%0], [%1], 16;" :: "r"(dst), "l"(src) : "memory");
}
#define CP_COMMIT() asm volatile("cp.async.commit_group;" ::: "memory")
#define CP_WAIT(n)  asm volatile("cp.async.wait_group %0;" :: "n"(n) : "memory")

__device__ __forceinline__ void ldsm4(uint32_t& r0, uint32_t& r1, uint32_t& r2, uint32_t& r3,
                                      uint32_t addr) {
    asm volatile("ldmatrix.sync.aligned.m8n8.x4.shared.b16 {%0,%1,%2,%3}, [%4];"
                 : "=r"(r0), "=r"(r1), "=r"(r2), "=r"(r3) : "r"(addr));
}
__device__ __forceinline__ void mma16816(float* c, const uint32_t* a, uint32_t b0, uint32_t b1) {
    asm volatile(
        "mma.sync.aligned.m16n8k16.row.col.f32.f16.f16.f32 "
        "{%0,%1,%2,%3}, {%4,%5,%6,%7}, {%8,%9}, {%0,%1,%2,%3};"
        : "+f"(c[0]), "+f"(c[1]), "+f"(c[2]), "+f"(c[3])
        : "r"(a[0]), "r"(a[1]), "r"(a[2]), "r"(a[3]), "r"(b0), "r"(b1));
}
__device__ __forceinline__ uint32_t pack2(float lo, float hi) {
    __half2 h = __floats2half2_rn(lo, hi);
    return *(uint32_t*)&h;
}

// Binarized weight sign(W) as fp16 (+-1 exact), prepared per launch.
__device__ __align__(16) __half g_bsign[N_DIM * K_DIM];

__global__ void prep_bsign(const float* __restrict__ W) {
    int i = blockIdx.x * blockDim.x + threadIdx.x;
    if (i < N_DIM * K_DIM) {
        float w = W[i];
        g_bsign[i] = __float2half((w > 0.f) ? 1.f : ((w < 0.f) ? -1.f : 0.f));
    }
}

__global__ __launch_bounds__(THREADS, 1)
void binlin_gemm(const float* __restrict__ x,
                 const float* __restrict__ scale,
                 const float* __restrict__ bias,
                 float* __restrict__ out) {
    extern __shared__ char smem[];
    float* sScale = (float*)(smem + OFF_SCALE);
    float* sBias  = (float*)(smem + OFF_BIAS);
    const uint32_t sAu = smem_u32(smem + OFF_A);
    const uint32_t sBu = smem_u32(smem + OFF_B);

    const int tid  = threadIdx.x;
    const int wid  = tid >> 5;
    const int lane = tid & 31;
    const int wm   = wid & 3;        // 0..3 (M, 32 rows each)
    const int wn   = wid >> 2;       // 0..3 (N, 64 cols each)
    const int g    = lane >> 2;      // 0..7
    const int t    = lane & 3;       // 0..3

    const int m_base = blockIdx.x * M_CTA;
    const float* xbase = x + (size_t)m_base * K_DIM;

    // ---- scale/bias (full N) ----
    if (tid < 256) {
        sScale[tid] = scale[tid];
        sBias[tid]  = bias[tid];
    }

    // A-chunk loader: thread handles items tid, tid+512 of 1024 x 16B
    const int lrow0 = tid >> 3;             // item0 row  (0..63)
    const int lq0   = tid & 7;
    // item1 = tid + 512 -> row + 64, same q
    auto issue_chunk = [&](int c) {
        const uint32_t buf = sAu + (uint32_t)(c & (RING - 1)) * CH_BYTES;
        const float* src = xbase + c * K_CHUNK;
        cp16(buf + lrow0 * 144 + lq0 * 16, src + (size_t)lrow0 * K_DIM + lq0 * 4);
        cp16(buf + (lrow0 + 64) * 144 + lq0 * 16, src + (size_t)(lrow0 + 64) * K_DIM + lq0 * 4);
    };

    // ---- prologue: B + chunk0 (group0), chunk1 (g1), chunk2 (g2) ----
    #pragma unroll
    for (int i = 0; i < 16; i++) {
        int c   = tid + THREADS * i;        // 0..8191
        int row = c >> 5;
        int q   = c & 31;
        cp16(sBu + row * (LDB * 2) + q * 16, g_bsign + row * K_DIM + q * 8);
    }
    issue_chunk(0); CP_COMMIT();
    issue_chunk(1); CP_COMMIT();
    issue_chunk(2); CP_COMMIT();

    // ---- per-thread B ldmatrix base ----
    const uint32_t bAddr = sBu + ((wn * 64 + (lane & 15)) * LDB + (lane >> 4) * 8) * 2;

    // A fp32 smem per-thread row bases (within chunk): rows wm*32 + {i*16} + {g, g+8}
    const uint32_t aRow0 = (uint32_t)(wm * 32 + g) * 144;        // tile i=0, row g
    // offsets: +8*144 for g+8; +16*144 for tile i=1

    float acc[2][8][4];
    #pragma unroll
    for (int i = 0; i < 2; i++)
        #pragma unroll
        for (int j = 0; j < 8; j++)
            #pragma unroll
            for (int e = 0; e < 4; e++)
                acc[i][j][e] = 0.f;

    uint32_t bfr[4][4];   // [n16 group][4] regs: [n0-7/kLo, n8-15/kLo, n0-7/kHi, n8-15/kHi]

    // ---- chunk loop: 8 chunks of K=32 (2 k16-steps each) ----
    #pragma unroll
    for (int c = 0; c < N_CHUNKS; c++) {
        if (c < 6)      { CP_WAIT(2); }
        else if (c == 6){ CP_WAIT(1); }
        else            { CP_WAIT(0); }
        __syncthreads();

        const uint32_t abuf = sAu + (uint32_t)(c & (RING - 1)) * CH_BYTES;

        #pragma unroll
        for (int step = 0; step < 2; step++) {
            const int ks = c * 2 + step;            // global k16 index
            const uint32_t ko = (uint32_t)ks * 32;  // B byte offset along k

            // B fragments
            #pragma unroll
            for (int p = 0; p < 4; p++)
                ldsm4(bfr[p][0], bfr[p][1], bfr[p][2], bfr[p][3],
                      bAddr + p * 16 * LDB * 2 + ko);

            // A fragments from fp32 smem: tiles i=0,1
            uint32_t afr[2][4];
            #pragma unroll
            for (int i = 0; i < 2; i++) {
                const uint32_t rb = abuf + aRow0 + i * (16 * 144)
                                  + (step * 16 + 2 * t) * 4;
                float2 vlo0 = *(const float2*)__cvta_shared_to_generic(rb);
                float2 vlo1 = *(const float2*)__cvta_shared_to_generic(rb + 8 * 144);
                float2 vhi0 = *(const float2*)__cvta_shared_to_generic(rb + 32);
                float2 vhi1 = *(const float2*)__cvta_shared_to_generic(rb + 8 * 144 + 32);
                afr[i][0] = pack2(vlo0.x, vlo0.y);
                afr[i][1] = pack2(vlo1.x, vlo1.y);
                afr[i][2] = pack2(vhi0.x, vhi0.y);
                afr[i][3] = pack2(vhi1.x, vhi1.y);
            }

            #pragma unroll
            for (int i = 0; i < 2; i++)
                #pragma unroll
                for (int j = 0; j < 8; j++) {
                    const int p = j >> 1, h = j & 1;
                    mma16816(acc[i][j], afr[i], bfr[p][h], bfr[p][h + 2]);
                }
        }

        if (c + 3 < N_CHUNKS) {
            issue_chunk(c + 3);
            CP_COMMIT();
        }
    }

    // ---- register epilogue: scale*acc + bias, direct STG ----
    #pragma unroll
    for (int i = 0; i < 2; i++) {
        const int r0 = m_base + wm * 32 + i * 16 + g;
        float* dst0 = out + (size_t)r0 * N_DIM + wn * 64;
        float* dst1 = dst0 + 8 * N_DIM;
        #pragma unroll
        for (int j = 0; j < 8; j++) {
            const int col = j * 8 + 2 * t;
            const float2 sc = *(const float2*)(sScale + wn * 64 + col);
            const float2 bi = *(const float2*)(sBias  + wn * 64 + col);
            float2 v0, v1;
            v0.x = acc[i][j][0] * sc.x + bi.x;
            v0.y = acc[i][j][1] * sc.y + bi.y;
            v1.x = acc[i][j][2] * sc.x + bi.x;
            v1.y = acc[i][j][3] * sc.y + bi.y;
            *(float2*)(dst0 + col) = v0;
            *(float2*)(dst1 + col) = v1;
        }
    }
}

extern "C" void kernel_launch(void* const* d_in, const int* in_sizes, int n_in,
                              void* d_out, int out_size) {
    const float* x     = (const float*)d_in[0];
    const float* W     = (const float*)d_in[1];
    const float* scale = (const float*)d_in[2];
    const float* bias  = (const float*)d_in[3];
    float* out = (float*)d_out;

    const int M = in_sizes[0] / K_DIM;       // 131072
    const int grid = M / M_CTA;              // 1024

    prep_bsign<<<(N_DIM * K_DIM + 255) / 256, 256>>>(W);

    cudaFuncSetAttribute(binlin_gemm, cudaFuncAttributeMaxDynamicSharedMemorySize, SMEM_TOTAL);
    binlin_gemm<<<grid, THREADS, SMEM_TOTAL>>>(x, scale, bias, out);
}